// round 15
// baseline (speedup 1.0000x reference)
#include <cuda_runtime.h>
#include <cuda_fp16.h>
#include <math.h>
#include <stdint.h>

#define N_NODES 100000
#define E_EDGES 1600000
#define V_IN    256
#define H_DIM   128
#define BN_EPS  1e-5f

// ---------------- scratch (static device globals; no allocs allowed) ----------------
__device__ __align__(16) float g_deg[N_NODES];                 // deg -> dinv (in place)
__device__ __align__(16) int   g_hist[N_NODES];
__device__ __align__(16) int   g_rowptr[N_NODES + 1];
__device__ __align__(16) int   g_cursor[N_NODES];
__device__ __align__(16) int   g_bsums[128];
__device__ __align__(16) int2  g_csr[E_EDGES];                 // {src, bitcast(u=dinv[src]*ew)}
__device__ __align__(16) __half2 g_bufE[(size_t)N_NODES * 64]; // xW1, fp16 pairs
__device__ __align__(16) float g_bufR[(size_t)N_NODES * H_DIM];// x Wres (residual, fp32)
__device__ __align__(16) __half2 g_bufB[(size_t)N_NODES * 64]; // h1, fp16 pairs
__device__ __align__(16) __half2 g_bufC[(size_t)N_NODES * 64]; // h1@W2, fp16 pairs
__device__ __align__(16) float g_s[N_NODES];                   // h2 @ W3
__device__ __align__(16) uint32_t g_B1[256 * 128];             // [W1|Wres] fp16 pairs [N][K/2]
__device__ __align__(16) uint32_t g_B2[128 * 64];              // W2 fp16 pairs [N][K/2]
__device__ __align__(16) float g_sc1[H_DIM];
__device__ __align__(16) float g_sh1[H_DIM];
__device__ __align__(16) float g_sc2[H_DIM];
__device__ __align__(16) float g_sh2[H_DIM];

// =================== fp16 helpers ===================
__device__ __forceinline__ uint32_t pack_f16x2(float x0, float x1) {
    __half2 h = __floats2half2_rn(x0, x1);      // lo = x0, hi = x1
    return *(uint32_t*)&h;
}
__device__ __forceinline__ void mma_f16(float* d, const uint32_t* a,
                                        uint32_t b0, uint32_t b1) {
    asm volatile(
        "mma.sync.aligned.m16n8k16.row.col.f32.f16.f16.f32 "
        "{%0,%1,%2,%3}, {%4,%5,%6,%7}, {%8,%9}, {%0,%1,%2,%3};"
        : "+f"(d[0]), "+f"(d[1]), "+f"(d[2]), "+f"(d[3])
        : "r"(a[0]), "r"(a[1]), "r"(a[2]), "r"(a[3]), "r"(b0), "r"(b1));
}

// ---------------- degree / histogram ----------------
__global__ void init_kernel(float* deg, int* hist, int n) {
    int i = blockIdx.x * blockDim.x + threadIdx.x;
    if (i < n) { deg[i] = 1.0f; hist[i] = 0; }
}
__global__ void deg_hist_kernel(const int* __restrict__ ei, const float* __restrict__ ew,
                                float* deg, int* hist, int e) {
    int idx = blockIdx.x * blockDim.x + threadIdx.x;
    if (idx < e) {
        int c = ei[e + idx];
        atomicAdd(&deg[c], ew[idx]);
        atomicAdd(&hist[c], 1);
    }
}
__global__ void deg_fin_kernel(float* deg, int n) {
    int i = blockIdx.x * blockDim.x + threadIdx.x;
    if (i < n) deg[i] = rsqrtf(deg[i]);
}

// ---------------- exclusive scan (3 kernels) ----------------
__global__ __launch_bounds__(1024) void scanA_kernel(const int* __restrict__ hist,
                                                     int* __restrict__ excl,
                                                     int* __restrict__ bsums, int n) {
    __shared__ int smw[32];
    int tid = threadIdx.x;
    int gid = blockIdx.x * 1024 + tid;
    int lane = tid & 31, wid = tid >> 5;
    int v = (gid < n) ? hist[gid] : 0;
    int x = v;
    #pragma unroll
    for (int o = 1; o < 32; o <<= 1) {
        int y = __shfl_up_sync(0xffffffffu, x, o);
        if (lane >= o) x += y;
    }
    if (lane == 31) smw[wid] = x;
    __syncthreads();
    if (wid == 0) {
        int s = smw[lane];
        #pragma unroll
        for (int o = 1; o < 32; o <<= 1) {
            int y = __shfl_up_sync(0xffffffffu, s, o);
            if (lane >= o) s += y;
        }
        smw[lane] = s;
    }
    __syncthreads();
    int woff = (wid > 0) ? smw[wid - 1] : 0;
    int incl = x + woff;
    if (gid <= n) excl[gid] = incl - v;
    if (tid == 1023) bsums[blockIdx.x] = incl;
}
__global__ void scanB_kernel(int* bsums, int nb) {
    __shared__ int ws[4];
    int tid = threadIdx.x;
    int lane = tid & 31, wid = tid >> 5;
    int v = (tid < nb) ? bsums[tid] : 0;
    int x = v;
    #pragma unroll
    for (int o = 1; o < 32; o <<= 1) {
        int y = __shfl_up_sync(0xffffffffu, x, o);
        if (lane >= o) x += y;
    }
    if (lane == 31) ws[wid] = x;
    __syncthreads();
    int add = 0;
    #pragma unroll
    for (int w = 0; w < 4; w++) add += (w < wid) ? ws[w] : 0;
    if (tid < nb) bsums[tid] = x + add - v;
}
__global__ void scanC_kernel(int* __restrict__ rowptr, int* __restrict__ cursor,
                             const int* __restrict__ bsums, int n, int e) {
    int gid = blockIdx.x * 1024 + threadIdx.x;
    if (gid < n) {
        int v = rowptr[gid] + bsums[blockIdx.x];
        rowptr[gid] = v;
        cursor[gid] = v;
    }
    if (gid == 0) rowptr[n] = e;
}

// ---------------- CSR fill ----------------
__global__ void fill_kernel(const int* __restrict__ ei, const float* __restrict__ ew,
                            const float* __restrict__ dinv,
                            int* __restrict__ cursor, int2* __restrict__ csr, int e) {
    int idx = blockIdx.x * blockDim.x + threadIdx.x;
    if (idx < e) {
        int r = ei[idx];
        int c = ei[e + idx];
        int pos = atomicAdd(&cursor[c], 1);
        csr[pos] = make_int2(r, __float_as_int(dinv[r] * ew[idx]));
    }
}

// ---------------- weight fp16 pack ----------------
__global__ void pack_B1_kernel(const float* __restrict__ W1, const float* __restrict__ Wres,
                               uint32_t* __restrict__ B) {
    int idx = blockIdx.x * blockDim.x + threadIdx.x;    // 32768; idx = n*128 + p
    int nn = idx >> 7, p = idx & 127;
    float v0, v1;
    if (nn < 128) { v0 = W1[(2 * p) * 128 + nn];          v1 = W1[(2 * p + 1) * 128 + nn]; }
    else          { v0 = Wres[(2 * p) * 128 + nn - 128];  v1 = Wres[(2 * p + 1) * 128 + nn - 128]; }
    B[idx] = pack_f16x2(v0, v1);
}
__global__ void pack_B2_kernel(const float* __restrict__ W2, uint32_t* __restrict__ B) {
    int idx = blockIdx.x * blockDim.x + threadIdx.x;    // 8192; idx = n*64 + p
    int nn = idx >> 6, p = idx & 63;
    B[idx] = pack_f16x2(W2[(2 * p) * 128 + nn], W2[(2 * p + 1) * 128 + nn]);
}
__global__ void bn_pre_kernel(const float* b1, const float* g1, const float* be1,
                              const float* m1, const float* v1,
                              const float* b2, const float* g2, const float* be2,
                              const float* m2, const float* v2,
                              float* sc1, float* sh1, float* sc2, float* sh2) {
    int f = threadIdx.x;
    float s1 = g1[f] * rsqrtf(v1[f] + BN_EPS);
    sc1[f] = s1;
    sh1[f] = (b1[f] - m1[f]) * s1 + be1[f];
    float s2 = g2[f] * rsqrtf(v2[f] + BN_EPS);
    sc2[f] = s2;
    sh2[f] = (b2[f] - m2[f]) * s2 + be2[f];
}

// ====== fp16 MMA GEMM with register double-buffering ======
// A: fp32 [M,K] (aHalf=0) or fp16 pairs [M,K/2] (aHalf=1)
// out tile n0==0 -> half2 Ch, n0==128 -> fp32 Cf
#define PSTRIDE 20
__global__ __launch_bounds__(256) void mma_gemm_kernel(
    const void* __restrict__ Av, const uint32_t* __restrict__ B,
    __half2* __restrict__ Ch, float* __restrict__ Cf, int M, int K, int aHalf) {
    __shared__ uint32_t As[128 * PSTRIDE];
    __shared__ uint32_t Bs[128 * PSTRIDE];

    const int tid = threadIdx.x;
    const int warpId = tid >> 5, lane = tid & 31;
    const int groupID = lane >> 2, tig = lane & 3;
    const int warpM = warpId & 3, warpN = warpId >> 2;
    const int m0 = blockIdx.y * 128;
    const int n0 = blockIdx.x * 128;
    const int Kp = K >> 1;
    const float* A32 = (const float*)Av;
    const uint32_t* A16 = (const uint32_t*)Av;

    // per-thread load coords (A: 4 groups, B: 2 groups)
    int aCf[4], aGr[4];
    #pragma unroll
    for (int t = 0; t < 4; t++) {
        int idx = tid + t * 256;
        int row = idx >> 3;
        aCf[t] = (idx & 7) * 4;
        int gr = m0 + row; if (gr >= M) gr = M - 1;
        aGr[t] = gr;
    }
    int bNn[2], bQ[2];
    #pragma unroll
    for (int t = 0; t < 2; t++) {
        int idx = tid + t * 256;
        bNn[t] = idx >> 2;
        bQ[t] = (idx & 3) * 4;
    }

    float acc[2][8][4];
    #pragma unroll
    for (int i = 0; i < 2; i++)
        #pragma unroll
        for (int j = 0; j < 8; j++)
            #pragma unroll
            for (int q = 0; q < 4; q++) acc[i][j][q] = 0.f;

    const int nChunks = K >> 5;

    // prefetch regs
    uint4 ar[4];          // fp32: bits of float4; fp16: .x,.y = uint2
    uint4 br[2];

    // load chunk 0
    #pragma unroll
    for (int t = 0; t < 4; t++) {
        if (!aHalf) ar[t] = *(const uint4*)(A32 + (size_t)aGr[t] * K + aCf[t]);
        else {
            uint2 v = *(const uint2*)(A16 + (size_t)aGr[t] * Kp + (aCf[t] >> 1));
            ar[t].x = v.x; ar[t].y = v.y;
        }
    }
    #pragma unroll
    for (int t = 0; t < 2; t++)
        br[t] = *(const uint4*)(B + (size_t)(n0 + bNn[t]) * Kp + bQ[t]);

    for (int c = 0; c < nChunks; c++) {
        // store prefetched chunk to smem
        #pragma unroll
        for (int t = 0; t < 4; t++) {
            uint2 h2;
            if (!aHalf) {
                h2.x = pack_f16x2(__uint_as_float(ar[t].x), __uint_as_float(ar[t].y));
                h2.y = pack_f16x2(__uint_as_float(ar[t].z), __uint_as_float(ar[t].w));
            } else {
                h2.x = ar[t].x; h2.y = ar[t].y;
            }
            int idx = tid + t * 256;
            int row = idx >> 3;
            *(uint2*)&As[row * PSTRIDE + (aCf[t] >> 1)] = h2;
        }
        #pragma unroll
        for (int t = 0; t < 2; t++)
            *(uint4*)&Bs[bNn[t] * PSTRIDE + bQ[t]] = br[t];
        __syncthreads();

        // prefetch next chunk (overlaps with MMA below)
        if (c + 1 < nChunks) {
            int co = (c + 1) * 32;
            #pragma unroll
            for (int t = 0; t < 4; t++) {
                if (!aHalf) ar[t] = *(const uint4*)(A32 + (size_t)aGr[t] * K + co + aCf[t]);
                else {
                    uint2 v = *(const uint2*)(A16 + (size_t)aGr[t] * Kp + ((co + aCf[t]) >> 1));
                    ar[t].x = v.x; ar[t].y = v.y;
                }
            }
            #pragma unroll
            for (int t = 0; t < 2; t++)
                br[t] = *(const uint4*)(B + (size_t)(n0 + bNn[t]) * Kp + (c + 1) * 16 + bQ[t]);
        }

        #pragma unroll
        for (int s = 0; s < 2; s++) {
            const int kp = s * 8 + tig;
            uint32_t ah[2][4];
            #pragma unroll
            for (int mt = 0; mt < 2; mt++) {
                int mb = warpM * 32 + mt * 16 + groupID;
                ah[mt][0] = As[mb * PSTRIDE + kp];
                ah[mt][1] = As[(mb + 8) * PSTRIDE + kp];
                ah[mt][2] = As[mb * PSTRIDE + kp + 4];
                ah[mt][3] = As[(mb + 8) * PSTRIDE + kp + 4];
            }
            #pragma unroll
            for (int nt = 0; nt < 8; nt++) {
                int nb = warpN * 64 + nt * 8 + groupID;
                uint32_t b0 = Bs[nb * PSTRIDE + kp];
                uint32_t b1 = Bs[nb * PSTRIDE + kp + 4];
                #pragma unroll
                for (int mt = 0; mt < 2; mt++)
                    mma_f16(acc[mt][nt], ah[mt], b0, b1);
            }
        }
        __syncthreads();
    }

    #pragma unroll
    for (int mt = 0; mt < 2; mt++) {
        int row = m0 + warpM * 32 + mt * 16 + groupID;
        int row2 = row + 8;
        #pragma unroll
        for (int nt = 0; nt < 8; nt++) {
            int col = warpN * 64 + nt * 8 + tig * 2;     // local 0..127
            if (n0 == 0) {
                if (row < M)
                    Ch[(size_t)row * 64 + (col >> 1)] =
                        __floats2half2_rn(acc[mt][nt][0], acc[mt][nt][1]);
                if (row2 < M)
                    Ch[(size_t)row2 * 64 + (col >> 1)] =
                        __floats2half2_rn(acc[mt][nt][2], acc[mt][nt][3]);
            } else {
                if (row < M)
                    *(float2*)(Cf + (size_t)row * H_DIM + col) =
                        make_float2(acc[mt][nt][0], acc[mt][nt][1]);
                if (row2 < M)
                    *(float2*)(Cf + (size_t)row2 * H_DIM + col) =
                        make_float2(acc[mt][nt][2], acc[mt][nt][3]);
            }
        }
    }
}

// ---- fp16 row gather helper: lane covers 4 floats (one uint2 = 2 half2) ----
__device__ __forceinline__ void h4_load(const __half2* __restrict__ base, int row, int lane,
                                        float2& a, float2& b) {
    uint2 raw = *((const uint2*)(base + (size_t)row * 64) + lane);
    a = __half22float2(*(__half2*)&raw.x);
    b = __half22float2(*(__half2*)&raw.y);
}

// ====== agg1 (fp16 src): bufB(fp16) = relu(BN1(dinv*(sum u*srcRow + dinv*selfRow))) ======
__global__ __launch_bounds__(256) void agg_feat_kernel(
    const int* __restrict__ rowptr, const int2* __restrict__ csr,
    const __half2* __restrict__ src, const float* __restrict__ dinv,
    __half2* __restrict__ dst,
    const float* __restrict__ bnSc, const float* __restrict__ bnSh, int n) {
    int i = (blockIdx.x * blockDim.x + threadIdx.x) >> 5;
    int lane = threadIdx.x & 31;
    if (i >= n) return;
    int p = rowptr[i], pEnd = rowptr[i + 1];
    float di = dinv[i];
    float2 sa, sb;
    h4_load(src, i, lane, sa, sb);
    float4 acc = make_float4(sa.x * di, sa.y * di, sb.x * di, sb.y * di);
    float4 acc2 = make_float4(0.f, 0.f, 0.f, 0.f);
    const unsigned FULL = 0xffffffffu;
    while (p < pEnd) {
        int take = pEnd - p; if (take > 32) take = 32;
        int2 ce = make_int2(0, 0);
        if (lane < take) ce = csr[p + lane];
        int j = 0;
        for (; j + 4 <= take; j += 4) {
            int s0 = __shfl_sync(FULL, ce.x, j);
            float u0 = __int_as_float(__shfl_sync(FULL, ce.y, j));
            int s1 = __shfl_sync(FULL, ce.x, j + 1);
            float u1 = __int_as_float(__shfl_sync(FULL, ce.y, j + 1));
            int s2 = __shfl_sync(FULL, ce.x, j + 2);
            float u2 = __int_as_float(__shfl_sync(FULL, ce.y, j + 2));
            int s3 = __shfl_sync(FULL, ce.x, j + 3);
            float u3 = __int_as_float(__shfl_sync(FULL, ce.y, j + 3));
            float2 a0, b0, a1, b1, a2, b2, a3, b3;
            h4_load(src, s0, lane, a0, b0);
            h4_load(src, s1, lane, a1, b1);
            h4_load(src, s2, lane, a2, b2);
            h4_load(src, s3, lane, a3, b3);
            acc.x = fmaf(u0, a0.x, acc.x);  acc2.x = fmaf(u1, a1.x, acc2.x);
            acc.y = fmaf(u0, a0.y, acc.y);  acc2.y = fmaf(u1, a1.y, acc2.y);
            acc.z = fmaf(u0, b0.x, acc.z);  acc2.z = fmaf(u1, b1.x, acc2.z);
            acc.w = fmaf(u0, b0.y, acc.w);  acc2.w = fmaf(u1, b1.y, acc2.w);
            acc.x = fmaf(u2, a2.x, acc.x);  acc2.x = fmaf(u3, a3.x, acc2.x);
            acc.y = fmaf(u2, a2.y, acc.y);  acc2.y = fmaf(u3, a3.y, acc2.y);
            acc.z = fmaf(u2, b2.x, acc.z);  acc2.z = fmaf(u3, b3.x, acc2.z);
            acc.w = fmaf(u2, b2.y, acc.w);  acc2.w = fmaf(u3, b3.y, acc2.w);
        }
        for (; j < take; j++) {
            int s0 = __shfl_sync(FULL, ce.x, j);
            float u0 = __int_as_float(__shfl_sync(FULL, ce.y, j));
            float2 a0, b0;
            h4_load(src, s0, lane, a0, b0);
            acc.x = fmaf(u0, a0.x, acc.x);
            acc.y = fmaf(u0, a0.y, acc.y);
            acc.z = fmaf(u0, b0.x, acc.z);
            acc.w = fmaf(u0, b0.y, acc.w);
        }
        p += take;
    }
    acc.x = (acc.x + acc2.x) * di;
    acc.y = (acc.y + acc2.y) * di;
    acc.z = (acc.z + acc2.z) * di;
    acc.w = (acc.w + acc2.w) * di;
    int f = lane * 4;
    float4 sc4 = *(const float4*)(bnSc + f);
    float4 sh4 = *(const float4*)(bnSh + f);
    acc.x = fmaxf(fmaf(acc.x, sc4.x, sh4.x), 0.f);
    acc.y = fmaxf(fmaf(acc.y, sc4.y, sh4.y), 0.f);
    acc.z = fmaxf(fmaf(acc.z, sc4.z, sh4.z), 0.f);
    acc.w = fmaxf(fmaf(acc.w, sc4.w, sh4.w), 0.f);
    uint2 o;
    o.x = pack_f16x2(acc.x, acc.y);
    o.y = pack_f16x2(acc.z, acc.w);
    *((uint2*)(dst + (size_t)i * 64) + lane) = o;
}

// ====== agg2 (fp16 src) + epi2 fused: s[i] = relu(BN2(agg + res)) . W3 ======
__global__ __launch_bounds__(256) void agg2_epi_kernel(
    const int* __restrict__ rowptr, const int2* __restrict__ csr,
    const __half2* __restrict__ src, const float* __restrict__ res,
    const float* __restrict__ dinv,
    const float* __restrict__ sc2, const float* __restrict__ sh2,
    const float* __restrict__ W3, float* __restrict__ s, int n) {
    int i = (blockIdx.x * blockDim.x + threadIdx.x) >> 5;
    int lane = threadIdx.x & 31;
    if (i >= n) return;
    int p = rowptr[i], pEnd = rowptr[i + 1];
    float di = dinv[i];
    float2 sa, sb;
    h4_load(src, i, lane, sa, sb);
    float4 acc = make_float4(sa.x * di, sa.y * di, sb.x * di, sb.y * di);
    float4 acc2 = make_float4(0.f, 0.f, 0.f, 0.f);
    const unsigned FULL = 0xffffffffu;
    while (p < pEnd) {
        int take = pEnd - p; if (take > 32) take = 32;
        int2 ce = make_int2(0, 0);
        if (lane < take) ce = csr[p + lane];
        int j = 0;
        for (; j + 4 <= take; j += 4) {
            int s0 = __shfl_sync(FULL, ce.x, j);
            float u0 = __int_as_float(__shfl_sync(FULL, ce.y, j));
            int s1 = __shfl_sync(FULL, ce.x, j + 1);
            float u1 = __int_as_float(__shfl_sync(FULL, ce.y, j + 1));
            int s2 = __shfl_sync(FULL, ce.x, j + 2);
            float u2 = __int_as_float(__shfl_sync(FULL, ce.y, j + 2));
            int s3 = __shfl_sync(FULL, ce.x, j + 3);
            float u3 = __int_as_float(__shfl_sync(FULL, ce.y, j + 3));
            float2 a0, b0, a1, b1, a2, b2, a3, b3;
            h4_load(src, s0, lane, a0, b0);
            h4_load(src, s1, lane, a1, b1);
            h4_load(src, s2, lane, a2, b2);
            h4_load(src, s3, lane, a3, b3);
            acc.x = fmaf(u0, a0.x, acc.x);  acc2.x = fmaf(u1, a1.x, acc2.x);
            acc.y = fmaf(u0, a0.y, acc.y);  acc2.y = fmaf(u1, a1.y, acc2.y);
            acc.z = fmaf(u0, b0.x, acc.z);  acc2.z = fmaf(u1, b1.x, acc2.z);
            acc.w = fmaf(u0, b0.y, acc.w);  acc2.w = fmaf(u1, b1.y, acc2.w);
            acc.x = fmaf(u2, a2.x, acc.x);  acc2.x = fmaf(u3, a3.x, acc2.x);
            acc.y = fmaf(u2, a2.y, acc.y);  acc2.y = fmaf(u3, a3.y, acc2.y);
            acc.z = fmaf(u2, b2.x, acc.z);  acc2.z = fmaf(u3, b3.x, acc2.z);
            acc.w = fmaf(u2, b2.y, acc.w);  acc2.w = fmaf(u3, b3.y, acc2.w);
        }
        for (; j < take; j++) {
            int s0 = __shfl_sync(FULL, ce.x, j);
            float u0 = __int_as_float(__shfl_sync(FULL, ce.y, j));
            float2 a0, b0;
            h4_load(src, s0, lane, a0, b0);
            acc.x = fmaf(u0, a0.x, acc.x);
            acc.y = fmaf(u0, a0.y, acc.y);
            acc.z = fmaf(u0, b0.x, acc.z);
            acc.w = fmaf(u0, b0.y, acc.w);
        }
        p += take;
    }
    acc.x += acc2.x; acc.y += acc2.y; acc.z += acc2.z; acc.w += acc2.w;
    int f = lane * 4;
    float4 r4  = *(const float4*)(res + (size_t)i * H_DIM + f);
    float4 sc4 = *(const float4*)(sc2 + f);
    float4 sh4 = *(const float4*)(sh2 + f);
    float4 w4  = *(const float4*)(W3 + f);
    float dot = 0.f;
    dot += fmaxf(fmaf(acc.x * di + r4.x, sc4.x, sh4.x), 0.f) * w4.x;
    dot += fmaxf(fmaf(acc.y * di + r4.y, sc4.y, sh4.y), 0.f) * w4.y;
    dot += fmaxf(fmaf(acc.z * di + r4.z, sc4.z, sh4.z), 0.f) * w4.z;
    dot += fmaxf(fmaf(acc.w * di + r4.w, sc4.w, sh4.w), 0.f) * w4.w;
    #pragma unroll
    for (int off = 16; off; off >>= 1)
        dot += __shfl_down_sync(FULL, dot, off);
    if (lane == 0) s[i] = dot;
}

// ====== layer-3 scalar aggregate (4-way unrolled) ======
__global__ void agg3_kernel(const int* __restrict__ rowptr, const int2* __restrict__ csr,
                            const float* __restrict__ s, const float* __restrict__ dinv,
                            const float* __restrict__ b3, float* __restrict__ out, int n) {
    int i = blockIdx.x * blockDim.x + threadIdx.x;
    if (i >= n) return;
    int p = rowptr[i], pEnd = rowptr[i + 1];
    float di = dinv[i];
    float a0 = di * s[i], a1 = 0.f, a2 = 0.f, a3 = 0.f;
    for (; p + 4 <= pEnd; p += 4) {
        int2 e0 = csr[p], e1 = csr[p + 1], e2 = csr[p + 2], e3 = csr[p + 3];
        a0 = fmaf(__int_as_float(e0.y), s[e0.x], a0);
        a1 = fmaf(__int_as_float(e1.y), s[e1.x], a1);
        a2 = fmaf(__int_as_float(e2.y), s[e2.x], a2);
        a3 = fmaf(__int_as_float(e3.y), s[e3.x], a3);
    }
    for (; p < pEnd; p++) {
        int2 e = csr[p];
        a0 = fmaf(__int_as_float(e.y), s[e.x], a0);
    }
    out[i] = fmaf(di, (a0 + a1) + (a2 + a3), b3[0]);
}

// ---------------- launch ----------------
extern "C" void kernel_launch(void* const* d_in, const int* in_sizes, int n_in,
                              void* d_out, int out_size) {
    const float* x    = (const float*)d_in[0];
    const int*   ei   = (const int*)d_in[1];     // int32 (jax downcasts int64)
    const float* ew   = (const float*)d_in[2];
    const float* W1   = (const float*)d_in[3];
    const float* b1   = (const float*)d_in[4];
    const float* W2   = (const float*)d_in[5];
    const float* b2   = (const float*)d_in[6];
    const float* W3   = (const float*)d_in[7];
    const float* b3   = (const float*)d_in[8];
    const float* Wres = (const float*)d_in[9];
    const float* g1   = (const float*)d_in[10];
    const float* be1  = (const float*)d_in[11];
    const float* m1   = (const float*)d_in[12];
    const float* v1   = (const float*)d_in[13];
    const float* g2   = (const float*)d_in[14];
    const float* be2  = (const float*)d_in[15];
    const float* m2   = (const float*)d_in[16];
    const float* v2   = (const float*)d_in[17];
    float* out = (float*)d_out;

    int n = in_sizes[0] / V_IN;   // 100000
    int e = in_sizes[2];          // 1600000

    float *deg, *bufR, *s, *sc1, *sh1, *sc2, *sh2;
    __half2 *bufE, *bufB, *bufC;
    int *hist, *rowptr, *cursor, *bsums;
    int2 *csr;
    uint32_t *B1, *B2;
    cudaGetSymbolAddress((void**)&deg,    g_deg);
    cudaGetSymbolAddress((void**)&hist,   g_hist);
    cudaGetSymbolAddress((void**)&rowptr, g_rowptr);
    cudaGetSymbolAddress((void**)&cursor, g_cursor);
    cudaGetSymbolAddress((void**)&bsums,  g_bsums);
    cudaGetSymbolAddress((void**)&csr,    g_csr);
    cudaGetSymbolAddress((void**)&bufE,   g_bufE);
    cudaGetSymbolAddress((void**)&bufR,   g_bufR);
    cudaGetSymbolAddress((void**)&bufB,   g_bufB);
    cudaGetSymbolAddress((void**)&bufC,   g_bufC);
    cudaGetSymbolAddress((void**)&s,      g_s);
    cudaGetSymbolAddress((void**)&B1,     g_B1);
    cudaGetSymbolAddress((void**)&B2,     g_B2);
    cudaGetSymbolAddress((void**)&sc1,    g_sc1);
    cudaGetSymbolAddress((void**)&sh1,    g_sh1);
    cudaGetSymbolAddress((void**)&sc2,    g_sc2);
    cudaGetSymbolAddress((void**)&sh2,    g_sh2);

    int nb_n   = (n + 255) / 256;
    int nb_e   = (e + 255) / 256;
    int nb_nw  = (n + 7) / 8;                 // warp per node
    int nbScan = (n + 1023) / 1024;           // 98
    int mTiles = (n + 127) / 128;

    // streams/events for graph-parallel branches (host objects; created once)
    static cudaStream_t st1 = nullptr, st2 = nullptr;
    static cudaEvent_t evRoot = nullptr, evCsr = nullptr, evSmall = nullptr;
    if (!st1) {
        cudaStreamCreateWithFlags(&st1, cudaStreamNonBlocking);
        cudaStreamCreateWithFlags(&st2, cudaStreamNonBlocking);
        cudaEventCreateWithFlags(&evRoot,  cudaEventDisableTiming);
        cudaEventCreateWithFlags(&evCsr,   cudaEventDisableTiming);
        cudaEventCreateWithFlags(&evSmall, cudaEventDisableTiming);
    }

    // fork
    cudaEventRecord(evRoot, 0);
    cudaStreamWaitEvent(st1, evRoot, 0);
    cudaStreamWaitEvent(st2, evRoot, 0);

    // branch st1: CSR build chain
    init_kernel<<<nb_n, 256, 0, st1>>>(deg, hist, n);
    deg_hist_kernel<<<nb_e, 256, 0, st1>>>(ei, ew, deg, hist, e);
    deg_fin_kernel<<<nb_n, 256, 0, st1>>>(deg, n);
    scanA_kernel<<<nbScan, 1024, 0, st1>>>(hist, rowptr, bsums, n);
    scanB_kernel<<<1, 128, 0, st1>>>(bsums, nbScan);
    scanC_kernel<<<nbScan, 1024, 0, st1>>>(rowptr, cursor, bsums, n, e);
    fill_kernel<<<nb_e, 256, 0, st1>>>(ei, ew, deg, cursor, csr, e);
    cudaEventRecord(evCsr, st1);

    // branch st2: small weight prep
    pack_B2_kernel<<<32, 256, 0, st2>>>(W2, B2);
    bn_pre_kernel<<<1, 128, 0, st2>>>(b1, g1, be1, m1, v1, b2, g2, be2, m2, v2,
                                      sc1, sh1, sc2, sh2);
    cudaEventRecord(evSmall, st2);

    // main branch: GEMM1 (independent of CSR): bufE(fp16) = x@W1, bufR(fp32) = x@Wres
    pack_B1_kernel<<<128, 256>>>(W1, Wres, B1);
    mma_gemm_kernel<<<dim3(2, mTiles), 256>>>(x, B1, bufE, bufR, n, 256, 0);

    // join
    cudaStreamWaitEvent(0, evCsr, 0);
    cudaStreamWaitEvent(0, evSmall, 0);

    // agg1 + BN1 + ReLU: bufB(fp16) = relu(BN1(A_hat @ bufE))
    agg_feat_kernel<<<nb_nw, 256>>>(rowptr, csr, bufE, deg, bufB, sc1, sh1, n);

    // GEMM2: bufC(fp16) = bufB(fp16) @ W2
    mma_gemm_kernel<<<dim3(1, mTiles), 256>>>(bufB, B2, bufC, nullptr, n, 128, 1);

    // agg2 + BN2 + res + ReLU + .W3: s
    agg2_epi_kernel<<<nb_nw, 256>>>(rowptr, csr, bufC, bufR, deg, sc2, sh2, W3, s, n);

    // layer 3 scalar aggregate -> out
    agg3_kernel<<<nb_n, 256>>>(rowptr, csr, s, deg, b3, out, n);
}

// round 16
// speedup vs baseline: 1.3891x; 1.3891x over previous
#include <cuda_runtime.h>
#include <cuda_fp16.h>
#include <math.h>
#include <stdint.h>

#define N_NODES 100000
#define E_EDGES 1600000
#define V_IN    256
#define H_DIM   128
#define BN_EPS  1e-5f

// ---------------- scratch (static device globals; no allocs allowed) ----------------
__device__ __align__(16) float g_deg[N_NODES];                 // deg -> dinv (in place)
__device__ __align__(16) int   g_hist[N_NODES];
__device__ __align__(16) int   g_rowptr[N_NODES + 1];
__device__ __align__(16) int   g_cursor[N_NODES];
__device__ __align__(16) int   g_bsums[128];
__device__ __align__(16) int2  g_csr[E_EDGES];                 // {src, bitcast(u=dinv[src]*ew)}
__device__ __align__(16) __half2 g_bufE[(size_t)N_NODES * 64]; // xW1, fp16 pairs
__device__ __align__(16) float g_bufR[(size_t)N_NODES * H_DIM];// x Wres (residual, fp32)
__device__ __align__(16) __half2 g_bufB[(size_t)N_NODES * 64]; // h1, fp16 pairs
__device__ __align__(16) __half2 g_bufC[(size_t)N_NODES * 64]; // h1@W2, fp16 pairs
__device__ __align__(16) float g_s[N_NODES];                   // h2 @ W3
__device__ __align__(16) uint32_t g_B1[256 * 128];             // [W1|Wres] fp16 pairs [N][K/2]
__device__ __align__(16) uint32_t g_B2[128 * 64];              // W2 fp16 pairs [N][K/2]
__device__ __align__(16) float g_sc1[H_DIM];
__device__ __align__(16) float g_sh1[H_DIM];
__device__ __align__(16) float g_sc2[H_DIM];
__device__ __align__(16) float g_sh2[H_DIM];

// =================== fp16 helpers ===================
__device__ __forceinline__ uint32_t pack_f16x2(float x0, float x1) {
    __half2 h = __floats2half2_rn(x0, x1);      // lo = x0, hi = x1
    return *(uint32_t*)&h;
}
__device__ __forceinline__ void mma_f16(float* d, const uint32_t* a,
                                        uint32_t b0, uint32_t b1) {
    asm volatile(
        "mma.sync.aligned.m16n8k16.row.col.f32.f16.f16.f32 "
        "{%0,%1,%2,%3}, {%4,%5,%6,%7}, {%8,%9}, {%0,%1,%2,%3};"
        : "+f"(d[0]), "+f"(d[1]), "+f"(d[2]), "+f"(d[3])
        : "r"(a[0]), "r"(a[1]), "r"(a[2]), "r"(a[3]), "r"(b0), "r"(b1));
}

// ---------------- degree / histogram ----------------
__global__ void init_kernel(float* deg, int* hist, int n) {
    int i = blockIdx.x * blockDim.x + threadIdx.x;
    if (i < n) { deg[i] = 1.0f; hist[i] = 0; }
}
__global__ void deg_hist_kernel(const int* __restrict__ ei, const float* __restrict__ ew,
                                float* deg, int* hist, int e) {
    int idx = blockIdx.x * blockDim.x + threadIdx.x;
    if (idx < e) {
        int c = ei[e + idx];
        atomicAdd(&deg[c], ew[idx]);
        atomicAdd(&hist[c], 1);
    }
}
__global__ void deg_fin_kernel(float* deg, int n) {
    int i = blockIdx.x * blockDim.x + threadIdx.x;
    if (i < n) deg[i] = rsqrtf(deg[i]);
}

// ---------------- exclusive scan (3 kernels) ----------------
__global__ __launch_bounds__(1024) void scanA_kernel(const int* __restrict__ hist,
                                                     int* __restrict__ excl,
                                                     int* __restrict__ bsums, int n) {
    __shared__ int smw[32];
    int tid = threadIdx.x;
    int gid = blockIdx.x * 1024 + tid;
    int lane = tid & 31, wid = tid >> 5;
    int v = (gid < n) ? hist[gid] : 0;
    int x = v;
    #pragma unroll
    for (int o = 1; o < 32; o <<= 1) {
        int y = __shfl_up_sync(0xffffffffu, x, o);
        if (lane >= o) x += y;
    }
    if (lane == 31) smw[wid] = x;
    __syncthreads();
    if (wid == 0) {
        int s = smw[lane];
        #pragma unroll
        for (int o = 1; o < 32; o <<= 1) {
            int y = __shfl_up_sync(0xffffffffu, s, o);
            if (lane >= o) s += y;
        }
        smw[lane] = s;
    }
    __syncthreads();
    int woff = (wid > 0) ? smw[wid - 1] : 0;
    int incl = x + woff;
    if (gid <= n) excl[gid] = incl - v;
    if (tid == 1023) bsums[blockIdx.x] = incl;
}
__global__ void scanB_kernel(int* bsums, int nb) {
    __shared__ int ws[4];
    int tid = threadIdx.x;
    int lane = tid & 31, wid = tid >> 5;
    int v = (tid < nb) ? bsums[tid] : 0;
    int x = v;
    #pragma unroll
    for (int o = 1; o < 32; o <<= 1) {
        int y = __shfl_up_sync(0xffffffffu, x, o);
        if (lane >= o) x += y;
    }
    if (lane == 31) ws[wid] = x;
    __syncthreads();
    int add = 0;
    #pragma unroll
    for (int w = 0; w < 4; w++) add += (w < wid) ? ws[w] : 0;
    if (tid < nb) bsums[tid] = x + add - v;
}
__global__ void scanC_kernel(int* __restrict__ rowptr, int* __restrict__ cursor,
                             const int* __restrict__ bsums, int n, int e) {
    int gid = blockIdx.x * 1024 + threadIdx.x;
    if (gid < n) {
        int v = rowptr[gid] + bsums[blockIdx.x];
        rowptr[gid] = v;
        cursor[gid] = v;
    }
    if (gid == 0) rowptr[n] = e;
}

// ---------------- CSR fill ----------------
__global__ void fill_kernel(const int* __restrict__ ei, const float* __restrict__ ew,
                            const float* __restrict__ dinv,
                            int* __restrict__ cursor, int2* __restrict__ csr, int e) {
    int idx = blockIdx.x * blockDim.x + threadIdx.x;
    if (idx < e) {
        int r = ei[idx];
        int c = ei[e + idx];
        int pos = atomicAdd(&cursor[c], 1);
        csr[pos] = make_int2(r, __float_as_int(dinv[r] * ew[idx]));
    }
}

// ---------------- weight fp16 pack ----------------
__global__ void pack_B1_kernel(const float* __restrict__ W1, const float* __restrict__ Wres,
                               uint32_t* __restrict__ B) {
    int idx = blockIdx.x * blockDim.x + threadIdx.x;    // 32768; idx = n*128 + p
    int nn = idx >> 7, p = idx & 127;
    float v0, v1;
    if (nn < 128) { v0 = W1[(2 * p) * 128 + nn];          v1 = W1[(2 * p + 1) * 128 + nn]; }
    else          { v0 = Wres[(2 * p) * 128 + nn - 128];  v1 = Wres[(2 * p + 1) * 128 + nn - 128]; }
    B[idx] = pack_f16x2(v0, v1);
}
__global__ void pack_B2_kernel(const float* __restrict__ W2, uint32_t* __restrict__ B) {
    int idx = blockIdx.x * blockDim.x + threadIdx.x;    // 8192; idx = n*64 + p
    int nn = idx >> 6, p = idx & 63;
    B[idx] = pack_f16x2(W2[(2 * p) * 128 + nn], W2[(2 * p + 1) * 128 + nn]);
}
__global__ void bn_pre_kernel(const float* b1, const float* g1, const float* be1,
                              const float* m1, const float* v1,
                              const float* b2, const float* g2, const float* be2,
                              const float* m2, const float* v2,
                              float* sc1, float* sh1, float* sc2, float* sh2) {
    int f = threadIdx.x;
    float s1 = g1[f] * rsqrtf(v1[f] + BN_EPS);
    sc1[f] = s1;
    sh1[f] = (b1[f] - m1[f]) * s1 + be1[f];
    float s2 = g2[f] * rsqrtf(v2[f] + BN_EPS);
    sc2[f] = s2;
    sh2[f] = (b2[f] - m2[f]) * s2 + be2[f];
}

// ====== fp16 MMA GEMM (single-buffered; r13 structure) ======
// A: fp32 [M,K] (aHalf=0) or fp16 pairs [M,K/2] (aHalf=1)
// out tile n0==0 -> half2 Ch, n0==128 -> fp32 Cf
#define PSTRIDE 20
__global__ __launch_bounds__(256) void mma_gemm_kernel(
    const void* __restrict__ Av, const uint32_t* __restrict__ B,
    __half2* __restrict__ Ch, float* __restrict__ Cf, int M, int K, int aHalf) {
    __shared__ uint32_t As[128 * PSTRIDE];
    __shared__ uint32_t Bs[128 * PSTRIDE];

    const int tid = threadIdx.x;
    const int warpId = tid >> 5, lane = tid & 31;
    const int groupID = lane >> 2, tig = lane & 3;
    const int warpM = warpId & 3, warpN = warpId >> 2;
    const int m0 = blockIdx.y * 128;
    const int n0 = blockIdx.x * 128;
    const int Kp = K >> 1;
    const float* A32 = (const float*)Av;
    const uint32_t* A16 = (const uint32_t*)Av;

    float acc[2][8][4];
    #pragma unroll
    for (int i = 0; i < 2; i++)
        #pragma unroll
        for (int j = 0; j < 8; j++)
            #pragma unroll
            for (int q = 0; q < 4; q++) acc[i][j][q] = 0.f;

    const int nChunks = K >> 5;
    for (int c = 0; c < nChunks; c++) {
        // ---- A tile: 128 rows x 32 k ----
        #pragma unroll
        for (int t = 0; t < 4; t++) {
            int idx = tid + t * 256;
            int row = idx >> 3;
            int cf = (idx & 7) * 4;
            int gr = m0 + row; if (gr >= M) gr = M - 1;
            uint2 h2;
            if (!aHalf) {
                float4 v = *(const float4*)(A32 + (size_t)gr * K + c * 32 + cf);
                h2.x = pack_f16x2(v.x, v.y);
                h2.y = pack_f16x2(v.z, v.w);
            } else {
                h2 = *(const uint2*)(A16 + (size_t)gr * Kp + ((c * 32 + cf) >> 1));
            }
            *(uint2*)&As[row * PSTRIDE + (cf >> 1)] = h2;
        }
        // ---- B tile: 128 n-rows x 16 pairs ----
        #pragma unroll
        for (int t = 0; t < 2; t++) {
            int idx = tid + t * 256;
            int nn = idx >> 2;
            int q = (idx & 3) * 4;
            size_t go = (size_t)(n0 + nn) * Kp + c * 16 + q;
            *(uint4*)&Bs[nn * PSTRIDE + q] = *(const uint4*)(B + go);
        }
        __syncthreads();

        #pragma unroll
        for (int s = 0; s < 2; s++) {
            const int kp = s * 8 + tig;
            uint32_t ah[2][4];
            #pragma unroll
            for (int mt = 0; mt < 2; mt++) {
                int mb = warpM * 32 + mt * 16 + groupID;
                ah[mt][0] = As[mb * PSTRIDE + kp];
                ah[mt][1] = As[(mb + 8) * PSTRIDE + kp];
                ah[mt][2] = As[mb * PSTRIDE + kp + 4];
                ah[mt][3] = As[(mb + 8) * PSTRIDE + kp + 4];
            }
            #pragma unroll
            for (int nt = 0; nt < 8; nt++) {
                int nb = warpN * 64 + nt * 8 + groupID;
                uint32_t b0 = Bs[nb * PSTRIDE + kp];
                uint32_t b1 = Bs[nb * PSTRIDE + kp + 4];
                #pragma unroll
                for (int mt = 0; mt < 2; mt++)
                    mma_f16(acc[mt][nt], ah[mt], b0, b1);
            }
        }
        __syncthreads();
    }

    #pragma unroll
    for (int mt = 0; mt < 2; mt++) {
        int row = m0 + warpM * 32 + mt * 16 + groupID;
        int row2 = row + 8;
        #pragma unroll
        for (int nt = 0; nt < 8; nt++) {
            int col = warpN * 64 + nt * 8 + tig * 2;     // local 0..127
            if (n0 == 0) {
                if (row < M)
                    Ch[(size_t)row * 64 + (col >> 1)] =
                        __floats2half2_rn(acc[mt][nt][0], acc[mt][nt][1]);
                if (row2 < M)
                    Ch[(size_t)row2 * 64 + (col >> 1)] =
                        __floats2half2_rn(acc[mt][nt][2], acc[mt][nt][3]);
            } else {
                if (row < M)
                    *(float2*)(Cf + (size_t)row * H_DIM + col) =
                        make_float2(acc[mt][nt][0], acc[mt][nt][1]);
                if (row2 < M)
                    *(float2*)(Cf + (size_t)row2 * H_DIM + col) =
                        make_float2(acc[mt][nt][2], acc[mt][nt][3]);
            }
        }
    }
}

// ---- fp16 row gather helper: lane covers 4 floats (one uint2 = 2 half2) ----
__device__ __forceinline__ void h4_load(const __half2* __restrict__ base, int row, int lane,
                                        float2& a, float2& b) {
    uint2 raw = *((const uint2*)(base + (size_t)row * 64) + lane);
    a = __half22float2(*(__half2*)&raw.x);
    b = __half22float2(*(__half2*)&raw.y);
}

// ====== agg1 (fp16 src): bufB(fp16) = relu(BN1(dinv*(sum u*srcRow + dinv*selfRow))) ======
__global__ __launch_bounds__(256) void agg_feat_kernel(
    const int* __restrict__ rowptr, const int2* __restrict__ csr,
    const __half2* __restrict__ src, const float* __restrict__ dinv,
    __half2* __restrict__ dst,
    const float* __restrict__ bnSc, const float* __restrict__ bnSh, int n) {
    int i = (blockIdx.x * blockDim.x + threadIdx.x) >> 5;
    int lane = threadIdx.x & 31;
    if (i >= n) return;
    int p = rowptr[i], pEnd = rowptr[i + 1];
    float di = dinv[i];
    float2 sa, sb;
    h4_load(src, i, lane, sa, sb);
    float4 acc = make_float4(sa.x * di, sa.y * di, sb.x * di, sb.y * di);
    float4 acc2 = make_float4(0.f, 0.f, 0.f, 0.f);
    const unsigned FULL = 0xffffffffu;
    while (p < pEnd) {
        int take = pEnd - p; if (take > 32) take = 32;
        int2 ce = make_int2(0, 0);
        if (lane < take) ce = csr[p + lane];
        int j = 0;
        for (; j + 4 <= take; j += 4) {
            int s0 = __shfl_sync(FULL, ce.x, j);
            float u0 = __int_as_float(__shfl_sync(FULL, ce.y, j));
            int s1 = __shfl_sync(FULL, ce.x, j + 1);
            float u1 = __int_as_float(__shfl_sync(FULL, ce.y, j + 1));
            int s2 = __shfl_sync(FULL, ce.x, j + 2);
            float u2 = __int_as_float(__shfl_sync(FULL, ce.y, j + 2));
            int s3 = __shfl_sync(FULL, ce.x, j + 3);
            float u3 = __int_as_float(__shfl_sync(FULL, ce.y, j + 3));
            float2 a0, b0, a1, b1, a2, b2, a3, b3;
            h4_load(src, s0, lane, a0, b0);
            h4_load(src, s1, lane, a1, b1);
            h4_load(src, s2, lane, a2, b2);
            h4_load(src, s3, lane, a3, b3);
            acc.x = fmaf(u0, a0.x, acc.x);  acc2.x = fmaf(u1, a1.x, acc2.x);
            acc.y = fmaf(u0, a0.y, acc.y);  acc2.y = fmaf(u1, a1.y, acc2.y);
            acc.z = fmaf(u0, b0.x, acc.z);  acc2.z = fmaf(u1, b1.x, acc2.z);
            acc.w = fmaf(u0, b0.y, acc.w);  acc2.w = fmaf(u1, b1.y, acc2.w);
            acc.x = fmaf(u2, a2.x, acc.x);  acc2.x = fmaf(u3, a3.x, acc2.x);
            acc.y = fmaf(u2, a2.y, acc.y);  acc2.y = fmaf(u3, a3.y, acc2.y);
            acc.z = fmaf(u2, b2.x, acc.z);  acc2.z = fmaf(u3, b3.x, acc2.z);
            acc.w = fmaf(u2, b2.y, acc.w);  acc2.w = fmaf(u3, b3.y, acc2.w);
        }
        for (; j < take; j++) {
            int s0 = __shfl_sync(FULL, ce.x, j);
            float u0 = __int_as_float(__shfl_sync(FULL, ce.y, j));
            float2 a0, b0;
            h4_load(src, s0, lane, a0, b0);
            acc.x = fmaf(u0, a0.x, acc.x);
            acc.y = fmaf(u0, a0.y, acc.y);
            acc.z = fmaf(u0, b0.x, acc.z);
            acc.w = fmaf(u0, b0.y, acc.w);
        }
        p += take;
    }
    acc.x = (acc.x + acc2.x) * di;
    acc.y = (acc.y + acc2.y) * di;
    acc.z = (acc.z + acc2.z) * di;
    acc.w = (acc.w + acc2.w) * di;
    int f = lane * 4;
    float4 sc4 = *(const float4*)(bnSc + f);
    float4 sh4 = *(const float4*)(bnSh + f);
    acc.x = fmaxf(fmaf(acc.x, sc4.x, sh4.x), 0.f);
    acc.y = fmaxf(fmaf(acc.y, sc4.y, sh4.y), 0.f);
    acc.z = fmaxf(fmaf(acc.z, sc4.z, sh4.z), 0.f);
    acc.w = fmaxf(fmaf(acc.w, sc4.w, sh4.w), 0.f);
    uint2 o;
    o.x = pack_f16x2(acc.x, acc.y);
    o.y = pack_f16x2(acc.z, acc.w);
    *((uint2*)(dst + (size_t)i * 64) + lane) = o;
}

// ====== agg2 (fp16 src) + epi2 fused: s[i] = relu(BN2(agg + res)) . W3 ======
__global__ __launch_bounds__(256) void agg2_epi_kernel(
    const int* __restrict__ rowptr, const int2* __restrict__ csr,
    const __half2* __restrict__ src, const float* __restrict__ res,
    const float* __restrict__ dinv,
    const float* __restrict__ sc2, const float* __restrict__ sh2,
    const float* __restrict__ W3, float* __restrict__ s, int n) {
    int i = (blockIdx.x * blockDim.x + threadIdx.x) >> 5;
    int lane = threadIdx.x & 31;
    if (i >= n) return;
    int p = rowptr[i], pEnd = rowptr[i + 1];
    float di = dinv[i];
    float2 sa, sb;
    h4_load(src, i, lane, sa, sb);
    float4 acc = make_float4(sa.x * di, sa.y * di, sb.x * di, sb.y * di);
    float4 acc2 = make_float4(0.f, 0.f, 0.f, 0.f);
    const unsigned FULL = 0xffffffffu;
    while (p < pEnd) {
        int take = pEnd - p; if (take > 32) take = 32;
        int2 ce = make_int2(0, 0);
        if (lane < take) ce = csr[p + lane];
        int j = 0;
        for (; j + 4 <= take; j += 4) {
            int s0 = __shfl_sync(FULL, ce.x, j);
            float u0 = __int_as_float(__shfl_sync(FULL, ce.y, j));
            int s1 = __shfl_sync(FULL, ce.x, j + 1);
            float u1 = __int_as_float(__shfl_sync(FULL, ce.y, j + 1));
            int s2 = __shfl_sync(FULL, ce.x, j + 2);
            float u2 = __int_as_float(__shfl_sync(FULL, ce.y, j + 2));
            int s3 = __shfl_sync(FULL, ce.x, j + 3);
            float u3 = __int_as_float(__shfl_sync(FULL, ce.y, j + 3));
            float2 a0, b0, a1, b1, a2, b2, a3, b3;
            h4_load(src, s0, lane, a0, b0);
            h4_load(src, s1, lane, a1, b1);
            h4_load(src, s2, lane, a2, b2);
            h4_load(src, s3, lane, a3, b3);
            acc.x = fmaf(u0, a0.x, acc.x);  acc2.x = fmaf(u1, a1.x, acc2.x);
            acc.y = fmaf(u0, a0.y, acc.y);  acc2.y = fmaf(u1, a1.y, acc2.y);
            acc.z = fmaf(u0, b0.x, acc.z);  acc2.z = fmaf(u1, b1.x, acc2.z);
            acc.w = fmaf(u0, b0.y, acc.w);  acc2.w = fmaf(u1, b1.y, acc2.w);
            acc.x = fmaf(u2, a2.x, acc.x);  acc2.x = fmaf(u3, a3.x, acc2.x);
            acc.y = fmaf(u2, a2.y, acc.y);  acc2.y = fmaf(u3, a3.y, acc2.y);
            acc.z = fmaf(u2, b2.x, acc.z);  acc2.z = fmaf(u3, b3.x, acc2.z);
            acc.w = fmaf(u2, b2.y, acc.w);  acc2.w = fmaf(u3, b3.y, acc2.w);
        }
        for (; j < take; j++) {
            int s0 = __shfl_sync(FULL, ce.x, j);
            float u0 = __int_as_float(__shfl_sync(FULL, ce.y, j));
            float2 a0, b0;
            h4_load(src, s0, lane, a0, b0);
            acc.x = fmaf(u0, a0.x, acc.x);
            acc.y = fmaf(u0, a0.y, acc.y);
            acc.z = fmaf(u0, b0.x, acc.z);
            acc.w = fmaf(u0, b0.y, acc.w);
        }
        p += take;
    }
    acc.x += acc2.x; acc.y += acc2.y; acc.z += acc2.z; acc.w += acc2.w;
    int f = lane * 4;
    float4 r4  = *(const float4*)(res + (size_t)i * H_DIM + f);
    float4 sc4 = *(const float4*)(sc2 + f);
    float4 sh4 = *(const float4*)(sh2 + f);
    float4 w4  = *(const float4*)(W3 + f);
    float dot = 0.f;
    dot += fmaxf(fmaf(acc.x * di + r4.x, sc4.x, sh4.x), 0.f) * w4.x;
    dot += fmaxf(fmaf(acc.y * di + r4.y, sc4.y, sh4.y), 0.f) * w4.y;
    dot += fmaxf(fmaf(acc.z * di + r4.z, sc4.z, sh4.z), 0.f) * w4.z;
    dot += fmaxf(fmaf(acc.w * di + r4.w, sc4.w, sh4.w), 0.f) * w4.w;
    #pragma unroll
    for (int off = 16; off; off >>= 1)
        dot += __shfl_down_sync(FULL, dot, off);
    if (lane == 0) s[i] = dot;
}

// ====== layer-3 scalar aggregate (4-way unrolled) ======
__global__ void agg3_kernel(const int* __restrict__ rowptr, const int2* __restrict__ csr,
                            const float* __restrict__ s, const float* __restrict__ dinv,
                            const float* __restrict__ b3, float* __restrict__ out, int n) {
    int i = blockIdx.x * blockDim.x + threadIdx.x;
    if (i >= n) return;
    int p = rowptr[i], pEnd = rowptr[i + 1];
    float di = dinv[i];
    float a0 = di * s[i], a1 = 0.f, a2 = 0.f, a3 = 0.f;
    for (; p + 4 <= pEnd; p += 4) {
        int2 e0 = csr[p], e1 = csr[p + 1], e2 = csr[p + 2], e3 = csr[p + 3];
        a0 = fmaf(__int_as_float(e0.y), s[e0.x], a0);
        a1 = fmaf(__int_as_float(e1.y), s[e1.x], a1);
        a2 = fmaf(__int_as_float(e2.y), s[e2.x], a2);
        a3 = fmaf(__int_as_float(e3.y), s[e3.x], a3);
    }
    for (; p < pEnd; p++) {
        int2 e = csr[p];
        a0 = fmaf(__int_as_float(e.y), s[e.x], a0);
    }
    out[i] = fmaf(di, (a0 + a1) + (a2 + a3), b3[0]);
}

// ---------------- launch ----------------
extern "C" void kernel_launch(void* const* d_in, const int* in_sizes, int n_in,
                              void* d_out, int out_size) {
    const float* x    = (const float*)d_in[0];
    const int*   ei   = (const int*)d_in[1];     // int32 (jax downcasts int64)
    const float* ew   = (const float*)d_in[2];
    const float* W1   = (const float*)d_in[3];
    const float* b1   = (const float*)d_in[4];
    const float* W2   = (const float*)d_in[5];
    const float* b2   = (const float*)d_in[6];
    const float* W3   = (const float*)d_in[7];
    const float* b3   = (const float*)d_in[8];
    const float* Wres = (const float*)d_in[9];
    const float* g1   = (const float*)d_in[10];
    const float* be1  = (const float*)d_in[11];
    const float* m1   = (const float*)d_in[12];
    const float* v1   = (const float*)d_in[13];
    const float* g2   = (const float*)d_in[14];
    const float* be2  = (const float*)d_in[15];
    const float* m2   = (const float*)d_in[16];
    const float* v2   = (const float*)d_in[17];
    float* out = (float*)d_out;

    int n = in_sizes[0] / V_IN;   // 100000
    int e = in_sizes[2];          // 1600000

    float *deg, *bufR, *s, *sc1, *sh1, *sc2, *sh2;
    __half2 *bufE, *bufB, *bufC;
    int *hist, *rowptr, *cursor, *bsums;
    int2 *csr;
    uint32_t *B1, *B2;
    cudaGetSymbolAddress((void**)&deg,    g_deg);
    cudaGetSymbolAddress((void**)&hist,   g_hist);
    cudaGetSymbolAddress((void**)&rowptr, g_rowptr);
    cudaGetSymbolAddress((void**)&cursor, g_cursor);
    cudaGetSymbolAddress((void**)&bsums,  g_bsums);
    cudaGetSymbolAddress((void**)&csr,    g_csr);
    cudaGetSymbolAddress((void**)&bufE,   g_bufE);
    cudaGetSymbolAddress((void**)&bufR,   g_bufR);
    cudaGetSymbolAddress((void**)&bufB,   g_bufB);
    cudaGetSymbolAddress((void**)&bufC,   g_bufC);
    cudaGetSymbolAddress((void**)&s,      g_s);
    cudaGetSymbolAddress((void**)&B1,     g_B1);
    cudaGetSymbolAddress((void**)&B2,     g_B2);
    cudaGetSymbolAddress((void**)&sc1,    g_sc1);
    cudaGetSymbolAddress((void**)&sh1,    g_sh1);
    cudaGetSymbolAddress((void**)&sc2,    g_sc2);
    cudaGetSymbolAddress((void**)&sh2,    g_sh2);

    int nb_n   = (n + 255) / 256;
    int nb_e   = (e + 255) / 256;
    int nb_nw  = (n + 7) / 8;                 // warp per node
    int nbScan = (n + 1023) / 1024;           // 98
    int mTiles = (n + 127) / 128;

    // streams/events for graph-parallel branches (host objects; created once)
    static cudaStream_t st1 = nullptr, st2 = nullptr;
    static cudaEvent_t evRoot = nullptr, evCsr = nullptr, evSmall = nullptr;
    if (!st1) {
        cudaStreamCreateWithFlags(&st1, cudaStreamNonBlocking);
        cudaStreamCreateWithFlags(&st2, cudaStreamNonBlocking);
        cudaEventCreateWithFlags(&evRoot,  cudaEventDisableTiming);
        cudaEventCreateWithFlags(&evCsr,   cudaEventDisableTiming);
        cudaEventCreateWithFlags(&evSmall, cudaEventDisableTiming);
    }

    // fork
    cudaEventRecord(evRoot, 0);
    cudaStreamWaitEvent(st1, evRoot, 0);
    cudaStreamWaitEvent(st2, evRoot, 0);

    // branch st1: CSR build chain
    init_kernel<<<nb_n, 256, 0, st1>>>(deg, hist, n);
    deg_hist_kernel<<<nb_e, 256, 0, st1>>>(ei, ew, deg, hist, e);
    deg_fin_kernel<<<nb_n, 256, 0, st1>>>(deg, n);
    scanA_kernel<<<nbScan, 1024, 0, st1>>>(hist, rowptr, bsums, n);
    scanB_kernel<<<1, 128, 0, st1>>>(bsums, nbScan);
    scanC_kernel<<<nbScan, 1024, 0, st1>>>(rowptr, cursor, bsums, n, e);
    fill_kernel<<<nb_e, 256, 0, st1>>>(ei, ew, deg, cursor, csr, e);
    cudaEventRecord(evCsr, st1);

    // branch st2: small weight prep
    pack_B2_kernel<<<32, 256, 0, st2>>>(W2, B2);
    bn_pre_kernel<<<1, 128, 0, st2>>>(b1, g1, be1, m1, v1, b2, g2, be2, m2, v2,
                                      sc1, sh1, sc2, sh2);
    cudaEventRecord(evSmall, st2);

    // main branch: GEMM1 (independent of CSR): bufE(fp16) = x@W1, bufR(fp32) = x@Wres
    pack_B1_kernel<<<128, 256>>>(W1, Wres, B1);
    mma_gemm_kernel<<<dim3(2, mTiles), 256>>>(x, B1, bufE, bufR, n, 256, 0);

    // join
    cudaStreamWaitEvent(0, evCsr, 0);
    cudaStreamWaitEvent(0, evSmall, 0);

    // agg1 + BN1 + ReLU: bufB(fp16) = relu(BN1(A_hat @ bufE))
    agg_feat_kernel<<<nb_nw, 256>>>(rowptr, csr, bufE, deg, bufB, sc1, sh1, n);

    // GEMM2: bufC(fp16) = bufB(fp16) @ W2
    mma_gemm_kernel<<<dim3(1, mTiles), 256>>>(bufB, B2, bufC, nullptr, n, 128, 1);

    // agg2 + BN2 + res + ReLU + .W3: s
    agg2_epi_kernel<<<nb_nw, 256>>>(rowptr, csr, bufC, bufR, deg, sc2, sh2, W3, s, n);

    // layer 3 scalar aggregate -> out
    agg3_kernel<<<nb_n, 256>>>(rowptr, csr, s, deg, b3, out, n);
}